// round 16
// baseline (speedup 1.0000x reference)
#include <cuda_runtime.h>

// BilinearInterpolation: B=16, H=W=512, C=16 fp32.
// R16: R15's smem y-table diet combined with ROWS=16 (fewer row-gathers per
// output: 2+15s rows per 16 outputs vs 2*(2+7s) per 2x8). Per-row body:
// LDS.128 + 2 SEL + 2 LDG.128 + 8 f32x2 + STG.128. launch_bounds(256,8),
// branch-free select advance, thread-per-quad, f32x2 packed math, __stcs.

#define BB 16
#define HH 512
#define WW 512
#define ROWS 16

typedef unsigned long long u64;

__device__ __forceinline__ u64 pk2(float v) {
    u64 r; asm("mov.b64 %0, {%1, %1};" : "=l"(r) : "f"(v)); return r;
}
__device__ __forceinline__ u64 mul2(u64 a, u64 b) {
    u64 r; asm("mul.rn.f32x2 %0, %1, %2;" : "=l"(r) : "l"(a), "l"(b)); return r;
}
__device__ __forceinline__ u64 fma2(u64 a, u64 b, u64 c) {
    u64 r; asm("fma.rn.f32x2 %0, %1, %2, %3;" : "=l"(r) : "l"(a), "l"(b), "l"(c)); return r;
}

struct H2 { u64 x, y; };   // horizontal interpolant of one input row (4 floats)

__device__ __forceinline__ H2 hload(const ulonglong2* __restrict__ row,
                                    int c0, int c1, u64 dx0, u64 dx1)
{
    const ulonglong2 p0 = __ldg(row + c0);
    const ulonglong2 p1 = __ldg(row + c1);
    H2 h;
    h.x = fma2(dx1, p0.x, mul2(dx0, p1.x));
    h.y = fma2(dx1, p0.y, mul2(dx0, p1.y));
    return h;
}

__global__ void __launch_bounds__(256, 8)
bilinear_tab16_kernel(const ulonglong2* __restrict__ X,
                      const float* __restrict__ scale,
                      const float* __restrict__ translate,
                      ulonglong2* __restrict__ out)
{
    __shared__ int4 ytab[ROWS];   // per row: {y0, y1*W*4, bits(dy0), bits(dy1)}

    const int t   = threadIdx.x;
    const int b   = blockIdx.z;            // uniform
    const int oy0 = blockIdx.y * ROWS;     // uniform

    // ---- uniform batch params ----
    const float s  = __ldg(&scale[b]);
    const float tx = __ldg(&translate[2 * b]);
    const float ty = __ldg(&translate[2 * b + 1]);

    // ---- y-table: threads 0..ROWS-1 compute one row each ----
    if (t < ROWS) {
        const float yc = fmaf((float)(oy0 + t), 2.0f / 511.0f, -1.0f);
        const float y  = 0.5f * (fmaf(s, yc, ty) + 1.0f) * (float)HH;
        int y0 = (int)y;            // trunc toward zero (matches astype(int32))
        int y1 = y0 + 1;
        y0 = min(max(y0, 0), HH - 1);
        y1 = min(max(y1, 0), HH - 1);
        ytab[t] = make_int4(y0, y1 << 11,
                            __float_as_int(y - (float)y0),
                            __float_as_int((float)y1 - y));
    }

    // ---- per-thread x-side math (shared by all ROWS outputs) ----
    const int q  = t & 3;
    const int ox = (blockIdx.x << 6) + (t >> 2);
    const float xc = fmaf((float)ox, 2.0f / 511.0f, -1.0f);
    const float x  = 0.5f * (fmaf(s, xc, tx) + 1.0f) * (float)WW;
    int x0 = (int)x;
    int x1 = x0 + 1;
    x0 = min(max(x0, 0), WW - 1);
    x1 = min(max(x1, 0), WW - 1);
    const u64 dx1 = pk2((float)x1 - x);
    const u64 dx0 = pk2(x - (float)x0);

    const int c0 = (x0 << 2) + q;
    const int c1 = (x1 << 2) + q;

    const ulonglong2* __restrict__ Xb = X + b * (HH * WW * 4);
    ulonglong2* __restrict__ O = out + ((b * HH + oy0) << 11) + (blockIdx.x << 8) + t;

    __syncthreads();

    // ---- prologue: row 0 ----
    int4 e = ytab[0];
    int cury0 = e.x;
    H2 h0 = hload(Xb + (e.x << 11), c0, c1, dx0, dx1);
    H2 h1 = hload(Xb + e.y,         c0, c1, dx0, dx1);
    {
        const u64 dy0 = pk2(__int_as_float(e.z));
        const u64 dy1 = pk2(__int_as_float(e.w));
        ulonglong2 o;
        o.x = fma2(dy1, h0.x, mul2(dy0, h1.x));
        o.y = fma2(dy1, h0.y, mul2(dy0, h1.y));
        __stcs(O, o);
    }

    // ---- branch-free main loop ----
    #pragma unroll
    for (int r = 1; r < ROWS; ++r) {
        e = ytab[r];

        // register-select cache advance (s<1 => step 0 or 1; clamp-safe)
        const bool adv = (e.x != cury0);
        h0.x = adv ? h1.x : h0.x;
        h0.y = adv ? h1.y : h0.y;
        cury0 = e.x;

        // unconditional reload of the high row (L1/L2 hit when unchanged)
        h1 = hload(Xb + e.y, c0, c1, dx0, dx1);

        const u64 dy0 = pk2(__int_as_float(e.z));
        const u64 dy1 = pk2(__int_as_float(e.w));
        ulonglong2 o;
        o.x = fma2(dy1, h0.x, mul2(dy0, h1.x));
        o.y = fma2(dy1, h0.y, mul2(dy0, h1.y));
        __stcs(O + (r << 11), o);
    }
}

extern "C" void kernel_launch(void* const* d_in, const int* in_sizes, int n_in,
                              void* d_out, int out_size)
{
    const float* X         = (const float*)d_in[0];
    const float* scale     = (const float*)d_in[1];
    const float* translate = (const float*)d_in[2];

    dim3 grid(WW / 64, HH / ROWS, BB);   // (8, 32, 16) = 4096 blocks
    bilinear_tab16_kernel<<<grid, 256>>>((const ulonglong2*)X, scale, translate,
                                         (ulonglong2*)d_out);
}